// round 15
// baseline (speedup 1.0000x reference)
#include <cuda_runtime.h>
#include <cstdint>

#define NB 1024
#define NS 50
#define NH 64
#define NITEM 40000
#define TPB 256
#define NQ 256                // 256 CTAs, 4 rows each (2 pairs), single wave
#define ZBYTES 16000          // zero smem buffer; 40 * 16000 = 640000 B = 4 rows
#define NBULK 40

typedef unsigned long long u64;

__device__ __forceinline__ u64 pk(float lo, float hi) {
    u64 r; asm("mov.b64 %0, {%1, %2};" : "=l"(r) : "f"(lo), "f"(hi)); return r;
}
__device__ __forceinline__ void fma2(u64& d, u64 a, u64 b) {
    asm("fma.rn.f32x2 %0, %1, %2, %0;" : "+l"(d) : "l"(a), "l"(b));
}
__device__ __forceinline__ void add2(u64& d, u64 a) {
    asm("add.rn.f32x2 %0, %1, %0;" : "+l"(d) : "l"(a));
}
__device__ __forceinline__ float hsum2(u64 v) {
    float lo, hi; asm("mov.b64 {%0, %1}, %2;" : "=f"(lo), "=f"(hi) : "l"(v));
    return lo + hi;
}
__device__ __forceinline__ unsigned smem_u32(const void* p) {
    unsigned a;
    asm("{ .reg .u64 t; cvta.to.shared.u64 t, %1; cvt.u32.u64 %0, t; }" : "=r"(a) : "l"(p));
    return a;
}

__global__ __launch_bounds__(TPB, 2)
void rrd_all(const float* __restrict__ all_memory,
             const float* __restrict__ last_memory,
             const int*   __restrict__ seq_item,
             const float* __restrict__ Wr,
             const float* __restrict__ Ur,
             const float* __restrict__ Vr_w,
             float* __restrict__ out)
{
    const int tid = threadIdx.x;
    const int B0  = 4 * blockIdx.x;       // first of this CTA's 4 rows

    __shared__ __align__(16) float xs[2 * NS * NH];   // 25.6 KB (current pair)
    __shared__ float matW[NH * 65];                   // 16.6 KB pad-65
    __shared__ float matU[NH * 65];                   // 16.6 KB
    __shared__ __align__(16) float vals[2][NS * 68];  // 27.2 KB
    __shared__ __align__(16) float zbuf[ZBYTES / 4];  // 15.6 KB zeros (bulk source)
    __shared__ float lastm[2][NH];
    __shared__ float scores[2][64];
    __shared__ float probs4[4 * NS];
    __shared__ int   sitem4[4 * NS];

    float* rowbase = out + (size_t)B0 * NITEM;

    // ================= prologue: matrices + zbuf (once per CTA) =============
    {
        const float4 zf = make_float4(0.f, 0.f, 0.f, 0.f);
        for (int i = tid; i < ZBYTES / 16; i += TPB)
            reinterpret_cast<float4*>(zbuf)[i] = zf;
        const float4* w4 = reinterpret_cast<const float4*>(Wr);
        const float4* u4 = reinterpret_cast<const float4*>(Ur);
        for (int i = tid; i < NH * NH / 4; i += TPB) {
            int r = i >> 4, c = (i & 15) * 4;
            float4 w = w4[i], u = u4[i];
            float* dw = &matW[r * 65 + c];
            dw[0] = w.x; dw[1] = w.y; dw[2] = w.z; dw[3] = w.w;
            float* du = &matU[r * 65 + c];
            du[0] = u.x; du[1] = u.y; du[2] = u.z; du[3] = u.w;
        }
    }
    __syncthreads();

    // ---- fire ALL 40 bulk zero-stores for the 4 rows (drain all kernel) ----
    if (tid == 0) {
        asm volatile("fence.proxy.async.shared::cta;" ::: "memory");
        unsigned zsrc = smem_u32(zbuf);
        char* gdst = reinterpret_cast<char*>(rowbase);
        #pragma unroll
        for (int c = 0; c < NBULK; c++) {
            asm volatile("cp.async.bulk.global.shared::cta.bulk_group [%0], [%1], %2;"
                :: "l"(gdst + (size_t)c * ZBYTES), "r"(zsrc), "r"((unsigned)ZBYTES)
                : "memory");
        }
        asm volatile("cp.async.bulk.commit_group;" ::: "memory");
    }

    // ---- hoisted per-thread constants: Ur row k packed + vk ----
    const int k = tid & 63;
    const int g = tid >> 6;              // 0..3 (warp-uniform s-group)
    u64 urp[NH / 2];
    #pragma unroll
    for (int h = 0; h < NH / 2; h++)
        urp[h] = pk(matU[k * 65 + 2 * h], matU[k * 65 + 2 * h + 1]);
    const float vk = Vr_w[k];

    // ================= pair loop: 2 pairs of rows =================
    #pragma unroll
    for (int it = 0; it < 2; it++) {
        const int b0 = B0 + 2 * it;

        // ---- stage this pair: xs (2 rows), lastm, sitem ----
        const float4* am4 = reinterpret_cast<const float4*>(all_memory + (size_t)b0 * (NS * NH));
        for (int i = tid; i < 2 * NS * NH / 4; i += TPB)
            reinterpret_cast<float4*>(xs)[i] = am4[i];
        if (tid < 2 * NH) lastm[tid >> 6][tid & 63] = last_memory[b0 * NH + tid];
        if (tid < 2 * NS) sitem4[it * 2 * NS + tid] = seq_item[b0 * NS + tid];
        __syncthreads();

        // ---- lk[r] = sum_h last[r][h]*Wr[k,h] ----
        float lkA0 = 0.f, lkA1 = 0.f, lkB0 = 0.f, lkB1 = 0.f;
        #pragma unroll
        for (int h = 0; h < NH; h += 2) {
            float w0 = matW[k * 65 + h], w1 = matW[k * 65 + h + 1];
            lkA0 += lastm[0][h] * w0;  lkA1 += lastm[0][h + 1] * w1;
            lkB0 += lastm[1][h] * w0;  lkB1 += lastm[1][h + 1] * w1;
        }
        const float lk0 = lkA0 + lkA1;
        const float lk1 = lkB0 + lkB1;

        // ---- main loop: both rows interleaved (f32x2, 4 indep chains) ----
        #pragma unroll
        for (int j = 0; j < 13; j++) {
            const int s = 4 * j + g;                 // warp-uniform
            if (s < NS) {
                const ulonglong2* xrA = reinterpret_cast<const ulonglong2*>(xs + s * NH);
                const ulonglong2* xrB = reinterpret_cast<const ulonglong2*>(xs + (NS + s) * NH);
                u64 a0 = pk(lk0, 0.f), a1 = pk(0.f, 0.f);
                u64 c0 = pk(lk1, 0.f), c1 = pk(0.f, 0.f);
                #pragma unroll
                for (int i = 0; i < 16; i++) {
                    ulonglong2 wA = xrA[i], wB = xrB[i];
                    fma2(a0, wA.x, urp[2 * i]);
                    fma2(c0, wB.x, urp[2 * i]);
                    fma2(a1, wA.y, urp[2 * i + 1]);
                    fma2(c1, wB.y, urp[2 * i + 1]);
                }
                add2(a0, a1); add2(c0, c1);
                float accA = hsum2(a0), accB = hsum2(c0);
                float eA = __expf(2.0f * accA), eB = __expf(2.0f * accB);
                vals[0][s * 68 + k] = vk * (1.0f - __fdividef(2.0f, eA + 1.0f));
                vals[1][s * 68 + k] = vk * (1.0f - __fdividef(2.0f, eB + 1.0f));
            }
        }
        __syncthreads();   // vals ready

        // ---- flat reduction over k (all 256 threads; clamped shuffles) ----
        {
            const int s2 = tid >> 2, p = tid & 3;
            const int s2c = (s2 < NS) ? s2 : (NS - 1);
            #pragma unroll
            for (int r = 0; r < 2; r++) {
                const float4* vr = reinterpret_cast<const float4*>(&vals[r][s2c * 68 + p * 16]);
                float4 r0 = vr[0], r1 = vr[1], r2 = vr[2], r3 = vr[3];
                float sum = ((r0.x + r0.y) + (r0.z + r0.w)) + ((r1.x + r1.y) + (r1.z + r1.w))
                          + ((r2.x + r2.y) + (r2.z + r2.w)) + ((r3.x + r3.y) + (r3.z + r3.w));
                sum += __shfl_xor_sync(0xffffffffu, sum, 1);
                sum += __shfl_xor_sync(0xffffffffu, sum, 2);
                if (p == 0 && s2 < NS) scores[r][s2] = sum;
            }
        }
        __syncthreads();

        // ---- softmax: warp 0 -> row 0, warp 1 -> row 1 (Vr_b cancels) ----
        if (tid < 64) {
            const int r = tid >> 5;
            const int t = tid & 31;
            float v0 = (t      < NS) ? scores[r][t]      : -1e30f;
            float v1 = (t + 32 < NS) ? scores[r][t + 32] : -1e30f;
            float m = fmaxf(v0, v1);
            #pragma unroll
            for (int o = 16; o; o >>= 1)
                m = fmaxf(m, __shfl_xor_sync(0xffffffffu, m, o));
            float e0 = (t      < NS) ? __expf(v0 - m) : 0.f;
            float e1 = (t + 32 < NS) ? __expf(v1 - m) : 0.f;
            float ssum = e0 + e1;
            #pragma unroll
            for (int o = 16; o; o >>= 1)
                ssum += __shfl_xor_sync(0xffffffffu, ssum, o);
            float inv = 1.f / ssum;
            if (t      < NS) probs4[(it * 2 + r) * NS + t]      = e0 * inv;
            if (t + 32 < NS) probs4[(it * 2 + r) * NS + t + 32] = e1 * inv;
        }
        // no trailing sync needed: next iteration's staging touches xs/lastm
        // (last read ≥2 barriers ago) and the stage-sync orders everything.
    }

    // ---- drain all bulk zeros, then scatter all 4 rows ----
    if (tid == 0)
        asm volatile("cp.async.bulk.wait_group 0;" ::: "memory");
    __syncthreads();   // probs4/sitem4 published; zeros complete before atomics

    if (tid < 4 * NS) {
        const int r = tid / NS;
        atomicAdd(rowbase + (size_t)r * NITEM + sitem4[tid], probs4[tid]);
    }
}

extern "C" void kernel_launch(void* const* d_in, const int* in_sizes, int n_in,
                              void* d_out, int out_size)
{
    const float* all_memory  = (const float*)d_in[0];
    const float* last_memory = (const float*)d_in[1];
    const int*   seq_item    = (const int*)  d_in[2];
    const float* Wr          = (const float*)d_in[3];
    const float* Ur          = (const float*)d_in[4];
    const float* Vr_w        = (const float*)d_in[5];
    // d_in[6] = Vr_b — softmax shift-invariant, unused.
    float* out = (float*)d_out;

    rrd_all<<<NQ, TPB>>>(all_memory, last_memory, seq_item, Wr, Ur, Vr_w, out);
}

// round 16
// speedup vs baseline: 1.3328x; 1.3328x over previous
#include <cuda_runtime.h>
#include <cstdint>

#define NB 1024
#define NS 50
#define NH 64
#define NITEM 40000
#define TPB 256
#define NQ (NB / 2)           // 512 CTAs, 2 rows each
#define ZBYTES 16000          // zero smem buffer; 20 * 16000 = 320000 B = 2 rows
#define NBULK 20

typedef unsigned long long u64;

__device__ __forceinline__ u64 pk(float lo, float hi) {
    u64 r; asm("mov.b64 %0, {%1, %2};" : "=l"(r) : "f"(lo), "f"(hi)); return r;
}
__device__ __forceinline__ void fma2(u64& d, u64 a, u64 b) {
    asm("fma.rn.f32x2 %0, %1, %2, %0;" : "+l"(d) : "l"(a), "l"(b));
}
__device__ __forceinline__ void add2(u64& d, u64 a) {
    asm("add.rn.f32x2 %0, %1, %0;" : "+l"(d) : "l"(a));
}
__device__ __forceinline__ float hsum2(u64 v) {
    float lo, hi; asm("mov.b64 {%0, %1}, %2;" : "=f"(lo), "=f"(hi) : "l"(v));
    return lo + hi;
}
__device__ __forceinline__ unsigned smem_u32(const void* p) {
    unsigned a;
    asm("{ .reg .u64 t; cvta.to.shared.u64 t, %1; cvt.u32.u64 %0, t; }" : "=r"(a) : "l"(p));
    return a;
}

__device__ float g_probs[NB * NS];   // probs scratch between kernels

__global__ __launch_bounds__(TPB, 2)
void rrd_main(const float* __restrict__ all_memory,
              const float* __restrict__ last_memory,
              const float* __restrict__ Wr,
              const float* __restrict__ Ur,
              const float* __restrict__ Vr_w,
              float* __restrict__ out)
{
    const int q   = blockIdx.x;
    const int b0  = 2 * q;
    const int tid = threadIdx.x;

    __shared__ __align__(16) float xs[2 * NS * NH];   // 25.6 KB
    __shared__ float matW[NH * 65];                   // 16.6 KB pad-65
    __shared__ float matU[NH * 65];                   // 16.6 KB
    __shared__ __align__(16) float vals[2][NS * 68];  // 27.2 KB
    __shared__ __align__(16) float zbuf[ZBYTES / 4];  // 15.6 KB zeros (bulk source)
    __shared__ float lastm[2][NH];
    __shared__ float scores[2][64];

    float* rowbase = out + (size_t)b0 * NITEM;

    // ---- stage everything + zero the bulk source buffer ----
    const float4* am4 = reinterpret_cast<const float4*>(all_memory + (size_t)b0 * (NS * NH));
    for (int i = tid; i < 2 * NS * NH / 4; i += TPB)
        reinterpret_cast<float4*>(xs)[i] = am4[i];
    if (tid < 2 * NH) lastm[tid >> 6][tid & 63] = last_memory[b0 * NH + tid];
    {
        const float4 zf = make_float4(0.f, 0.f, 0.f, 0.f);
        for (int i = tid; i < ZBYTES / 16; i += TPB)
            reinterpret_cast<float4*>(zbuf)[i] = zf;
    }
    {
        const float4* w4 = reinterpret_cast<const float4*>(Wr);
        const float4* u4 = reinterpret_cast<const float4*>(Ur);
        for (int i = tid; i < NH * NH / 4; i += TPB) {
            int r = i >> 4, c = (i & 15) * 4;
            float4 w = w4[i], u = u4[i];
            float* dw = &matW[r * 65 + c];
            dw[0] = w.x; dw[1] = w.y; dw[2] = w.z; dw[3] = w.w;
            float* du = &matU[r * 65 + c];
            du[0] = u.x; du[1] = u.y; du[2] = u.z; du[3] = u.w;
        }
    }
    __syncthreads();

    // ---- thread 0: fire 20 async bulk zero-stores (no completion wait!) ----
    if (tid == 0) {
        unsigned zsrc = smem_u32(zbuf);
        asm volatile("fence.proxy.async.shared::cta;" ::: "memory");
        char* gdst = reinterpret_cast<char*>(rowbase);
        #pragma unroll
        for (int c = 0; c < NBULK; c++) {
            asm volatile("cp.async.bulk.global.shared::cta.bulk_group [%0], [%1], %2;"
                :: "l"(gdst + (size_t)c * ZBYTES), "r"(zsrc), "r"((unsigned)ZBYTES)
                : "memory");
        }
        asm volatile("cp.async.bulk.commit_group;" ::: "memory");
    }

    // ================= compute: ALL 8 warps =================
    {
        const int k = tid & 63;
        const int g = tid >> 6;          // 0..3 (warp-uniform)

        // lk[r] = sum_h last[r][h]*Wr[k,h]
        float lkA0 = 0.f, lkA1 = 0.f, lkB0 = 0.f, lkB1 = 0.f;
        #pragma unroll
        for (int h = 0; h < NH; h += 2) {
            float w0 = matW[k * 65 + h], w1 = matW[k * 65 + h + 1];
            lkA0 += lastm[0][h] * w0;  lkA1 += lastm[0][h + 1] * w1;
            lkB0 += lastm[1][h] * w0;  lkB1 += lastm[1][h + 1] * w1;
        }
        const float lk0 = lkA0 + lkA1;
        const float lk1 = lkB0 + lkB1;

        // Ur row k packed (reused for both rows)
        u64 urp[NH / 2];
        #pragma unroll
        for (int h = 0; h < NH / 2; h++)
            urp[h] = pk(matU[k * 65 + 2 * h], matU[k * 65 + 2 * h + 1]);
        const float vk = Vr_w[k];

        #pragma unroll
        for (int j = 0; j < 13; j++) {
            const int s = 4 * j + g;                 // warp-uniform
            if (s < NS) {
                const ulonglong2* xrA = reinterpret_cast<const ulonglong2*>(xs + s * NH);
                const ulonglong2* xrB = reinterpret_cast<const ulonglong2*>(xs + (NS + s) * NH);
                u64 a0 = pk(lk0, 0.f), a1 = pk(0.f, 0.f);
                u64 c0 = pk(lk1, 0.f), c1 = pk(0.f, 0.f);
                #pragma unroll
                for (int i = 0; i < 16; i++) {
                    ulonglong2 wA = xrA[i], wB = xrB[i];
                    fma2(a0, wA.x, urp[2 * i]);
                    fma2(c0, wB.x, urp[2 * i]);
                    fma2(a1, wA.y, urp[2 * i + 1]);
                    fma2(c1, wB.y, urp[2 * i + 1]);
                }
                add2(a0, a1); add2(c0, c1);
                float accA = hsum2(a0), accB = hsum2(c0);
                float eA = __expf(2.0f * accA), eB = __expf(2.0f * accB);
                vals[0][s * 68 + k] = vk * (1.0f - __fdividef(2.0f, eA + 1.0f));
                vals[1][s * 68 + k] = vk * (1.0f - __fdividef(2.0f, eB + 1.0f));
            }
        }
    }
    __syncthreads();   // vals ready

    // ---- flat reduction over k (all 256 threads; clamped shuffles) ----
    {
        const int s2 = tid >> 2, p = tid & 3;
        const int s2c = (s2 < NS) ? s2 : (NS - 1);
        #pragma unroll
        for (int r = 0; r < 2; r++) {
            const float4* vr = reinterpret_cast<const float4*>(&vals[r][s2c * 68 + p * 16]);
            float4 r0 = vr[0], r1 = vr[1], r2 = vr[2], r3 = vr[3];
            float sum = ((r0.x + r0.y) + (r0.z + r0.w)) + ((r1.x + r1.y) + (r1.z + r1.w))
                      + ((r2.x + r2.y) + (r2.z + r2.w)) + ((r3.x + r3.y) + (r3.z + r3.w));
            sum += __shfl_xor_sync(0xffffffffu, sum, 1);
            sum += __shfl_xor_sync(0xffffffffu, sum, 2);
            if (p == 0 && s2 < NS) scores[r][s2] = sum;
        }
    }
    __syncthreads();

    // ---- softmax: warp 0 -> row 0, warp 1 -> row 1 (Vr_b cancels) ----
    if (tid < 64) {
        const int r = tid >> 5;
        const int t = tid & 31;
        float v0 = (t      < NS) ? scores[r][t]      : -1e30f;
        float v1 = (t + 32 < NS) ? scores[r][t + 32] : -1e30f;
        float m = fmaxf(v0, v1);
        #pragma unroll
        for (int o = 16; o; o >>= 1)
            m = fmaxf(m, __shfl_xor_sync(0xffffffffu, m, o));
        float e0 = (t      < NS) ? __expf(v0 - m) : 0.f;
        float e1 = (t + 32 < NS) ? __expf(v1 - m) : 0.f;
        float ssum = e0 + e1;
        #pragma unroll
        for (int o = 16; o; o >>= 1)
            ssum += __shfl_xor_sync(0xffffffffu, ssum, o);
        float inv = 1.f / ssum;
        if (t      < NS) g_probs[(b0 + r) * NS + t]      = e0 * inv;
        if (t + 32 < NS) g_probs[(b0 + r) * NS + t + 32] = e1 * inv;
    }

    // ---- wait only for the SOURCE READS (smem-reuse safety), then exit.
    // Write completion + ordering vs the scatter atomics is provided by the
    // kernel boundary (kernel2 launches after all of kernel1's writes land).
    __syncthreads();
    if (tid == 0)
        asm volatile("cp.async.bulk.wait_group.read 0;" ::: "memory");
}

// ============ Kernel 2: scatter-add probs into zeroed output (R9-proven) ====
__global__ __launch_bounds__(64)
void scatter_kernel(const int* __restrict__ seq_item, float* __restrict__ out)
{
    const int b = blockIdx.x;
    const int t = threadIdx.x;
    if (t < NS) {
        int item = seq_item[b * NS + t];
        atomicAdd(out + (size_t)b * NITEM + item, g_probs[b * NS + t]);
    }
}

extern "C" void kernel_launch(void* const* d_in, const int* in_sizes, int n_in,
                              void* d_out, int out_size)
{
    const float* all_memory  = (const float*)d_in[0];
    const float* last_memory = (const float*)d_in[1];
    const int*   seq_item    = (const int*)  d_in[2];
    const float* Wr          = (const float*)d_in[3];
    const float* Ur          = (const float*)d_in[4];
    const float* Vr_w        = (const float*)d_in[5];
    // d_in[6] = Vr_b — softmax shift-invariant, unused.
    float* out = (float*)d_out;

    rrd_main<<<NQ, TPB>>>(all_memory, last_memory, Wr, Ur, Vr_w, out);
    scatter_kernel<<<NB, 64>>>(seq_item, out);
}